// round 7
// baseline (speedup 1.0000x reference)
#include <cuda_runtime.h>
#include <stdint.h>

// Problem constants
#define IMGS 128          // 8 * 16 images
#define H 512
#define W 512
#define BINS 256          // 16 x 16 pooled GLCM
#define JBINS 4096        // 16 x 16 x 16 joint (q, a, b) histogram
#define SLABS 8           // row-slabs per image (= CTAs per image)
#define RPS (H / SLABS)   // 64 rows per CTA
#define TPB 128           // 4 warps; each warp owns a 128-column strip

#define FULLMASK 0xffffffffu

// Allocation-free scratch (statically zero-initialized; self-cleaning per run).
__device__ unsigned int g_counts[IMGS * BINS];
__device__ unsigned int g_tick[IMGS];    // entropy ticket
__device__ float        g_ent[IMGS];

// ---------------------------------------------------------------------------
// Kernel 1: joint-pair GLCM histogram + last-CTA entropy. Grid (SLABS, IMGS).
// NO inter-CTA spin: the ticket winner (last CTA to flush) computes entropy
// and exits — forward progress never depends on co-residency.
//
// Per pixel (i,j) the reference pools 4 relations (jnp.roll semantics):
//   s0 = q[i, j-1]  (0deg)    s1 = q[i-1, j+1] (45deg)
//   s2 = q[i-1, j]  (90deg)   s3 = q[i-1, j-1] (135deg)
// We record them with TWO atomics into J[q][a][b] (4096 bins):
//   J[q][s1][s2] += 1   and   J[q][s0][s3] += 1
// Pooled counts are recovered exactly as
//   counts[q][s] = sum_b J[q][s][b] + sum_a J[q][a][s].
// ---------------------------------------------------------------------------
__global__ __launch_bounds__(TPB) void glcm_hist_k(const float* __restrict__ x) {
    __shared__ unsigned int J[JBINS];    // 16 KB per-CTA joint histogram
    __shared__ float red[TPB];
    __shared__ int is_last_s;

    const int t   = threadIdx.x;
    const int wq  = t >> 5;
    const int ln  = t & 31;
    const int img = blockIdx.y;
    const float* __restrict__ base = x + (size_t)img * (H * W);

    // zero joint histogram (vector stores)
    {
        uint4 z = make_uint4(0u, 0u, 0u, 0u);
        uint4* Jv = (uint4*)J;
        #pragma unroll
        for (int i = t; i < JBINS / 4; i += TPB) Jv[i] = z;
    }
    __syncthreads();

    const int r0  = blockIdx.x * RPS;
    const int c0  = wq * 128 + ln * 4;             // this lane's 4 columns
    const int jl  = (wq * 128 + W - 1) & (W - 1);  // col left of warp strip
    const int jr  = (wq * 128 + 128)   & (W - 1);  // col right of warp strip
    const int lnL = (ln + 31) & 31;
    const int lnR = (ln + 1)  & 31;

    // Prologue: quantize wrapped previous row (r0-1 mod H) into pp.
    unsigned pp;
    {
        const int ip = (r0 + H - 1) & (H - 1);
        float4 v = *(const float4*)(base + (size_t)ip * W + c0);
        int a0 = (int)(v.x * 15.0f);          // FMUL + trunc: bit-exact vs ref
        int a1 = (int)(v.y * 15.0f);
        int a2 = (int)(v.z * 15.0f);
        int a3 = (int)(v.w * 15.0f);
        pp = (unsigned)a0 | ((unsigned)a1 << 8) | ((unsigned)a2 << 16) | ((unsigned)a3 << 24);
    }

    for (int r = 0; r < RPS; r++) {
        const int i  = r0 + r;
        const int ip = (i + H - 1) & (H - 1);

        float4 v = *(const float4*)(base + (size_t)i * W + c0);
        const unsigned q0 = (unsigned)(int)(v.x * 15.0f);
        const unsigned q1 = (unsigned)(int)(v.y * 15.0f);
        const unsigned q2 = (unsigned)(int)(v.z * 15.0f);
        const unsigned q3 = (unsigned)(int)(v.w * 15.0f);
        const unsigned cc = q0 | (q1 << 8) | (q2 << 16) | (q3 << 24);

        // Cross-lane neighbors (warp-strip edges patched by scalar loads).
        unsigned left_cur   = __shfl_sync(FULLMASK, cc >> 24, lnL);   // cur [c0-1]
        unsigned left_prev  = __shfl_sync(FULLMASK, pp >> 24, lnL);   // prev[c0-1]
        unsigned right_prev = __shfl_sync(FULLMASK, pp & 0xffu, lnR); // prev[c0+4]
        if (ln == 0) {
            left_cur  = (unsigned)(int)(base[(size_t)i  * W + jl] * 15.0f);
            left_prev = (unsigned)(int)(base[(size_t)ip * W + jl] * 15.0f);
        }
        if (ln == 31) {
            right_prev = (unsigned)(int)(base[(size_t)ip * W + jr] * 15.0f);
        }

        const unsigned p0 =  pp        & 0xffu;
        const unsigned p1 = (pp >> 8)  & 0xffu;
        const unsigned p2 = (pp >> 16) & 0xffu;
        const unsigned p3 =  pp >> 24;

        // px0: q=q0, s45=p1, s90=p0, s0=left_cur, s135=left_prev
        atomicAdd(&J[(q0 << 8) | (p1 << 4) | p0], 1u);
        atomicAdd(&J[(q0 << 8) | (left_cur << 4) | left_prev], 1u);
        // px1: q=q1, s45=p2, s90=p1, s0=q0, s135=p0
        atomicAdd(&J[(q1 << 8) | (p2 << 4) | p1], 1u);
        atomicAdd(&J[(q1 << 8) | (q0 << 4) | p0], 1u);
        // px2: q=q2, s45=p3, s90=p2, s0=q1, s135=p1
        atomicAdd(&J[(q2 << 8) | (p3 << 4) | p2], 1u);
        atomicAdd(&J[(q2 << 8) | (q1 << 4) | p1], 1u);
        // px3: q=q3, s45=right_prev, s90=p3, s0=q2, s135=p2
        atomicAdd(&J[(q3 << 8) | (right_prev << 4) | p3], 1u);
        atomicAdd(&J[(q3 << 8) | (q2 << 4) | p2], 1u);

        pp = cc;
    }

    // Flush: collapse J (4096) -> pooled bins (256), add to per-image global.
    // counts[q*16+s] = sum_b J[q*256 + s*16 + b] + sum_a J[q*256 + a*16 + s]
    __syncthreads();
    #pragma unroll
    for (int b = t; b < BINS; b += TPB) {      // 2 bins per thread
        const int q = b >> 4, s = b & 15;
        unsigned sum = 0u;
        const unsigned* Jq = &J[q << 8];
        #pragma unroll
        for (int k = 0; k < 16; k++) sum += Jq[(s << 4) | k];   // row: s45/s0 = s
        #pragma unroll
        for (int k = 0; k < 16; k++) sum += Jq[(k << 4) | s];   // col: s90/s135 = s
        atomicAdd(&g_counts[img * BINS + b], sum);
    }

    // Ticket: last CTA of this image computes entropy + self-cleans. No spin.
    __threadfence();
    if (t == 0) {
        unsigned tk = atomicAdd(&g_tick[img], 1u);
        is_last_s = (tk == SLABS - 1);
    }
    __syncthreads();
    if (!is_last_s) return;
    __threadfence();   // acquire: all 8 CTAs' flushes visible

    const float inv_total = 1.0f / (4.0f * H * W);
    float acc = 0.0f;
    #pragma unroll
    for (int b = t; b < BINS; b += TPB) {
        const float p = (float)g_counts[img * BINS + b] * inv_total;
        acc += -p * logf(p + 1e-10f);
        g_counts[img * BINS + b] = 0u;   // self-clean for next replay
    }
    red[t] = acc;
    __syncthreads();
    #pragma unroll
    for (int s = TPB / 2; s > 0; s >>= 1) {
        if (t < s) red[t] += red[t + s];
        __syncthreads();
    }
    if (t == 0) {
        g_ent[img]  = red[0];
        g_tick[img] = 0u;                // self-clean ticket
    }
}

// ---------------------------------------------------------------------------
// Kernel 2: broadcast entropy. 4 CTAs per image, 256 threads each.
// ---------------------------------------------------------------------------
__global__ __launch_bounds__(256) void bcast_k(float* __restrict__ out) {
    const int img  = blockIdx.x >> 2;
    const int part = blockIdx.x & 3;
    const float e  = g_ent[img];
    const float4 val = make_float4(e, e, e, e);

    float4* o = (float4*)(out + (size_t)img * (H * W) + (size_t)part * (H * W / 4));
    #pragma unroll 4
    for (int k = threadIdx.x; k < (H * W / 4) / 4; k += 256)   // 16384 float4/part
        o[k] = val;
}

// ---------------------------------------------------------------------------
// Launch: histogram(+entropy tail) -> broadcast. 2 launches, graph-capturable.
// ---------------------------------------------------------------------------
extern "C" void kernel_launch(void* const* d_in, const int* in_sizes, int n_in,
                              void* d_out, int out_size) {
    const float* x = (const float*)d_in[0];
    float* out = (float*)d_out;
    (void)in_sizes; (void)n_in; (void)out_size;

    dim3 g(SLABS, IMGS);
    glcm_hist_k<<<g, TPB>>>(x);
    bcast_k<<<IMGS * 4, 256>>>(out);
}

// round 10
// speedup vs baseline: 1.4576x; 1.4576x over previous
#include <cuda_runtime.h>
#include <stdint.h>

// Problem constants
#define IMGS 128          // 8 * 16 images
#define H 512
#define W 512
#define BINS 256          // 16 x 16 pooled GLCM
#define JBINS 4096        // 16 x 16 x 16 joint (q, a, b) histogram
#define SLABS 8           // row-slabs per image (= CTAs per image)
#define RPS (H / SLABS)   // 64 rows per CTA
#define TPB 128           // 4 warps; each warp owns 16 FULL rows
#define RPW (RPS / 4)     // 16 rows per warp

#define FULLMASK 0xffffffffu

// Allocation-free scratch (statically zero-initialized; self-cleaning per run).
__device__ unsigned int g_counts[IMGS * BINS];
__device__ unsigned int g_tick[IMGS];    // entropy ticket
__device__ float        g_ent[IMGS];

static __device__ __forceinline__ unsigned quant4(float4 v) {
    // FMUL + trunc toward zero: bit-exact vs reference (img * 15 -> int)
    unsigned a0 = (unsigned)(int)(v.x * 15.0f);
    unsigned a1 = (unsigned)(int)(v.y * 15.0f);
    unsigned a2 = (unsigned)(int)(v.z * 15.0f);
    unsigned a3 = (unsigned)(int)(v.w * 15.0f);
    return a0 | (a1 << 8) | (a2 << 16) | (a3 << 24);
}

// ---------------------------------------------------------------------------
// Kernel 1: joint-pair GLCM histogram + last-CTA entropy. Grid (SLABS, IMGS).
// Each warp owns 16 full 512-px rows. Lane ln, pass p covers columns
// [128p + 4ln, 128p + 4ln + 4). All horizontal neighbors (incl. the mod-512
// wrap) are in-warp: the shuffle rotation reader0<-provider31 coincides with
// the row wrap, so provider lane 31 supplies pass p-1 (and provider lane 0
// supplies pass p+1 for the right neighbor). No edge loads, no smem rows.
//
// Per pixel (i,j), 4 roll relations pooled (jnp.roll semantics):
//   s0 = q[i, j-1], s45 = q[i-1, j+1], s90 = q[i-1, j], s135 = q[i-1, j-1]
// recorded with TWO atomics into J[q][a][b] (4096 bins):
//   J[q][s45][s90]++ and J[q][s0][s135]++
// Pooled counts recovered exactly: counts[q][s] = row-sum + col-sum of J[q].
// ---------------------------------------------------------------------------
__global__ __launch_bounds__(TPB) void glcm_hist_k(const float* __restrict__ x) {
    __shared__ unsigned int J[JBINS];    // 16 KB per-CTA joint histogram
    __shared__ float red[TPB];
    __shared__ int is_last_s;

    const int t   = threadIdx.x;
    const int wq  = t >> 5;
    const int ln  = t & 31;
    const int img = blockIdx.y;
    const float* __restrict__ base = x + (size_t)img * (H * W);

    // zero joint histogram (vector stores)
    {
        uint4 z = make_uint4(0u, 0u, 0u, 0u);
        uint4* Jv = (uint4*)J;
        #pragma unroll
        for (int i = t; i < JBINS / 4; i += TPB) Jv[i] = z;
    }
    __syncthreads();

    const int r0w = blockIdx.x * RPS + wq * RPW;   // warp's first row
    const int lnL = (ln + 31) & 31;
    const int lnR = (ln + 1)  & 31;
    const int cbase = ln * 4;                      // column within a pass

    // Prologue: quantize wrapped previous row (r0w-1 mod H), all 4 passes.
    unsigned pp[4];
    {
        const int ip = (r0w + H - 1) & (H - 1);
        const float* rowp = base + (size_t)ip * W + cbase;
        #pragma unroll
        for (int p = 0; p < 4; p++)
            pp[p] = quant4(*(const float4*)(rowp + p * 128));
    }

    for (int r = 0; r < RPW; r++) {
        const int i = r0w + r;
        const float* rowc = base + (size_t)i * W + cbase;

        // 4 independent coalesced loads (MLP=4), then quantize.
        float4 v0 = *(const float4*)(rowc);
        float4 v1 = *(const float4*)(rowc + 128);
        float4 v2 = *(const float4*)(rowc + 256);
        float4 v3 = *(const float4*)(rowc + 384);
        unsigned cc[4];
        cc[0] = quant4(v0); cc[1] = quant4(v1);
        cc[2] = quant4(v2); cc[3] = quant4(v3);

        #pragma unroll
        for (int p = 0; p < 4; p++) {
            // Providers at the rotation seam supply the adjacent pass:
            //  reader 0 <- provider 31 : row wrap / pass-1 boundary
            //  reader 31 <- provider 0 : pass+1 boundary
            const unsigned lsrc_c = (ln == 31) ? cc[(p + 3) & 3] : cc[p];
            const unsigned lsrc_p = (ln == 31) ? pp[(p + 3) & 3] : pp[p];
            const unsigned rsrc_p = (ln == 0)  ? pp[(p + 1) & 3] : pp[p];
            const unsigned left_cur   = __shfl_sync(FULLMASK, lsrc_c >> 24,  lnL);
            const unsigned left_prev  = __shfl_sync(FULLMASK, lsrc_p >> 24,  lnL);
            const unsigned right_prev = __shfl_sync(FULLMASK, rsrc_p & 0xffu, lnR);

            const unsigned c  = cc[p];
            const unsigned pr = pp[p];
            const unsigned q0 =  c        & 0xffu;
            const unsigned q1 = (c >> 8)  & 0xffu;
            const unsigned q2 = (c >> 16) & 0xffu;
            const unsigned q3 =  c >> 24;
            const unsigned p0 =  pr        & 0xffu;
            const unsigned p1 = (pr >> 8)  & 0xffu;
            const unsigned p2 = (pr >> 16) & 0xffu;
            const unsigned p3 =  pr >> 24;

            // px0: q=q0, s45=p1, s90=p0, s0=left_cur, s135=left_prev
            atomicAdd(&J[(q0 << 8) | (p1 << 4) | p0], 1u);
            atomicAdd(&J[(q0 << 8) | (left_cur << 4) | left_prev], 1u);
            // px1: q=q1, s45=p2, s90=p1, s0=q0, s135=p0
            atomicAdd(&J[(q1 << 8) | (p2 << 4) | p1], 1u);
            atomicAdd(&J[(q1 << 8) | (q0 << 4) | p0], 1u);
            // px2: q=q2, s45=p3, s90=p2, s0=q1, s135=p1
            atomicAdd(&J[(q2 << 8) | (p3 << 4) | p2], 1u);
            atomicAdd(&J[(q2 << 8) | (q1 << 4) | p1], 1u);
            // px3: q=q3, s45=right_prev, s90=p3, s0=q2, s135=p2
            atomicAdd(&J[(q3 << 8) | (right_prev << 4) | p3], 1u);
            atomicAdd(&J[(q3 << 8) | (q2 << 4) | p2], 1u);
        }

        pp[0] = cc[0]; pp[1] = cc[1]; pp[2] = cc[2]; pp[3] = cc[3];
    }

    // Flush: collapse J (4096) -> pooled bins (256), add to per-image global.
    // counts[q*16+s] = sum_b J[q*256 + s*16 + b] + sum_a J[q*256 + a*16 + s]
    __syncthreads();
    #pragma unroll
    for (int b = t; b < BINS; b += TPB) {      // 2 bins per thread
        const int q = b >> 4, s = b & 15;
        unsigned sum = 0u;
        const unsigned* Jq = &J[q << 8];
        #pragma unroll
        for (int k = 0; k < 16; k++) sum += Jq[(s << 4) | k];   // row: s45/s0 = s
        #pragma unroll
        for (int k = 0; k < 16; k++) sum += Jq[(k << 4) | s];   // col: s90/s135 = s
        atomicAdd(&g_counts[img * BINS + b], sum);
    }

    // Ticket: last CTA of this image computes entropy + self-cleans. No spin.
    __threadfence();
    if (t == 0) {
        unsigned tk = atomicAdd(&g_tick[img], 1u);
        is_last_s = (tk == SLABS - 1);
    }
    __syncthreads();
    if (!is_last_s) return;
    __threadfence();   // acquire: all 8 CTAs' flushes visible

    const float inv_total = 1.0f / (4.0f * H * W);
    float acc = 0.0f;
    #pragma unroll
    for (int b = t; b < BINS; b += TPB) {
        const float p = (float)g_counts[img * BINS + b] * inv_total;
        acc += -p * logf(p + 1e-10f);
        g_counts[img * BINS + b] = 0u;   // self-clean for next replay
    }
    red[t] = acc;
    __syncthreads();
    #pragma unroll
    for (int s = TPB / 2; s > 0; s >>= 1) {
        if (t < s) red[t] += red[t + s];
        __syncthreads();
    }
    if (t == 0) {
        g_ent[img]  = red[0];
        g_tick[img] = 0u;                // self-clean ticket
    }
}

// ---------------------------------------------------------------------------
// Kernel 2: broadcast entropy. 4 CTAs per image, 256 threads each.
// ---------------------------------------------------------------------------
__global__ __launch_bounds__(256) void bcast_k(float* __restrict__ out) {
    const int img  = blockIdx.x >> 2;
    const int part = blockIdx.x & 3;
    const float e  = g_ent[img];
    const float4 val = make_float4(e, e, e, e);

    float4* o = (float4*)(out + (size_t)img * (H * W) + (size_t)part * (H * W / 4));
    #pragma unroll 4
    for (int k = threadIdx.x; k < (H * W / 4) / 4; k += 256)   // 16384 float4/part
        o[k] = val;
}

// ---------------------------------------------------------------------------
// Launch: histogram(+entropy tail) -> broadcast. 2 launches, graph-capturable.
// ---------------------------------------------------------------------------
extern "C" void kernel_launch(void* const* d_in, const int* in_sizes, int n_in,
                              void* d_out, int out_size) {
    const float* x = (const float*)d_in[0];
    float* out = (float*)d_out;
    (void)in_sizes; (void)n_in; (void)out_size;

    dim3 g(SLABS, IMGS);
    glcm_hist_k<<<g, TPB>>>(x);
    bcast_k<<<IMGS * 4, 256>>>(out);
}